// round 3
// baseline (speedup 1.0000x reference)
#include <cuda_runtime.h>
#include <cuda_bf16.h>

// ConsistencyLoss: KL(softmax(soft_targets/T) || softmax(logits/T)) * T^2, batchmean.
// B = 4.19M, C = 5, T = 3. HBM-bound streaming reduction (96 MB read).

#define NUM_CLASSES 5
#define TEMP 3.0f
#define INV_T (1.0f / 3.0f)

__device__ double g_sum;

__global__ void cl_init_kernel() {
    g_sum = 0.0;
}

// Dynamic index into a 5-register array without local-memory spill.
__device__ __forceinline__ float sel5(float l0, float l1, float l2, float l3, float l4, int i) {
    float r = l0;
    r = (i == 1) ? l1 : r;
    r = (i == 2) ? l2 : r;
    r = (i == 3) ? l3 : r;
    r = (i == 4) ? l4 : r;
    return r;
}

__device__ __forceinline__ float kl_sample(float s, float l0, float l1, float l2, float l3, float l4) {
    // ---- soft-target construction (two nonzero entries) ----
    float sc   = fminf(fmaxf(s * 5.0f, 0.0f), 4.0f);
    float fidx = floorf(sc);
    int   idx  = (int)fidx;
    float center = (fidx + 0.5f) * 0.2f;
    float dist   = fabsf(s - center) * 5.0f;
    bool lo = (idx > 0) && (s < center);
    bool hi = (idx < NUM_CLASSES - 1) && (s > center);
    bool nb = lo || hi;
    float main_val = nb ? (1.0f - dist) : 1.0f;
    float nb_val   = nb ? dist : 0.0f;
    int   nbi      = idx + (hi ? 1 : 0) - (lo ? 1 : 0);

    // ---- target softmax pieces (3 entries are exp(0)=1) ----
    float e_m  = __expf(main_val * INV_T);
    float e_nb = __expf(nb_val * INV_T);
    float Zp   = e_m + e_nb + 3.0f;
    float Sps  = e_m * main_val + e_nb * nb_val;   // Zp * sum(p * soft)

    // ---- logits log-softmax pieces ----
    float m = fmaxf(fmaxf(fmaxf(l0, l1), fmaxf(l2, l3)), l4);
    float Zq = __expf((l0 - m) * INV_T) + __expf((l1 - m) * INV_T)
             + __expf((l2 - m) * INV_T) + __expf((l3 - m) * INV_T)
             + __expf((l4 - m) * INV_T);
    float suml = l0 + l1 + l2 + l3 + l4;

    float lidx = sel5(l0, l1, l2, l3, l4, idx);
    float lnb  = sel5(l0, l1, l2, l3, l4, nbi);
    float pl   = suml + (e_m - 1.0f) * lidx + (e_nb - 1.0f) * lnb;  // Zp * sum(p * l)

    // kl_i = sum p*(soft - l + m)/T + logZq - logZp
    return (Sps - pl) / Zp * INV_T + m * INV_T + __logf(Zq) - __logf(Zp);
}

__global__ void __launch_bounds__(256)
cl_main_kernel(const float* __restrict__ qs, const float* __restrict__ lg, int n) {
    int n4  = n >> 2;                 // groups of 4 samples
    int gid = blockIdx.x * blockDim.x + threadIdx.x;
    int stride = gridDim.x * blockDim.x;

    float acc = 0.0f;

    // Vectorized main loop: each thread handles 4 samples -> 5x float4 logits + 1x float4 scores.
    const float4* qs4 = (const float4*)qs;
    const float4* lg4 = (const float4*)lg;
    for (int g = gid; g < n4; g += stride) {
        float4 s4 = qs4[g];
        float4 a = lg4[g * 5 + 0];
        float4 b = lg4[g * 5 + 1];
        float4 c = lg4[g * 5 + 2];
        float4 d = lg4[g * 5 + 3];
        float4 e = lg4[g * 5 + 4];
        // sample 0: a.x a.y a.z a.w b.x
        acc += kl_sample(s4.x, a.x, a.y, a.z, a.w, b.x);
        // sample 1: b.y b.z b.w c.x c.y
        acc += kl_sample(s4.y, b.y, b.z, b.w, c.x, c.y);
        // sample 2: c.z c.w d.x d.y d.z
        acc += kl_sample(s4.z, c.z, c.w, d.x, d.y, d.z);
        // sample 3: d.w e.x e.y e.z e.w
        acc += kl_sample(s4.w, d.w, e.x, e.y, e.z, e.w);
    }

    // Scalar tail (n % 4 samples) handled by the first few global threads.
    int rem_base = n4 << 2;
    if (gid < (n - rem_base)) {
        int i = rem_base + gid;
        const float* l = lg + (long)i * NUM_CLASSES;
        acc += kl_sample(qs[i], l[0], l[1], l[2], l[3], l[4]);
    }

    // ---- reduction: warp shuffle -> shared -> one double atomic per block ----
    #pragma unroll
    for (int off = 16; off > 0; off >>= 1)
        acc += __shfl_xor_sync(0xFFFFFFFF, acc, off);

    __shared__ float warp_sums[8];
    int lane = threadIdx.x & 31;
    int wid  = threadIdx.x >> 5;
    if (lane == 0) warp_sums[wid] = acc;
    __syncthreads();

    if (threadIdx.x == 0) {
        float bs = 0.0f;
        #pragma unroll
        for (int w = 0; w < 8; w++) bs += warp_sums[w];
        atomicAdd(&g_sum, (double)bs);
    }
}

__global__ void cl_finalize_kernel(float* out, int n) {
    out[0] = (float)(g_sum / (double)n * (double)(TEMP * TEMP));
}

extern "C" void kernel_launch(void* const* d_in, const int* in_sizes, int n_in,
                              void* d_out, int out_size) {
    const float* qs = (const float*)d_in[0];   // quality_score [B]
    const float* lg = (const float*)d_in[1];   // class_logits  [B, 5]
    float* out = (float*)d_out;
    int n = in_sizes[0];

    cl_init_kernel<<<1, 1>>>();

    int n4 = n >> 2;
    int threads = 256;
    int blocks = (n4 + threads - 1) / threads;
    if (blocks < 1) blocks = 1;
    cl_main_kernel<<<blocks, threads>>>(qs, lg, n);

    cl_finalize_kernel<<<1, 1>>>(out, n);
}